// round 10
// baseline (speedup 1.0000x reference)
#include <cuda_runtime.h>
#include <cuda_bf16.h>
#include <math.h>
#include <stdint.h>

#define C 128
#define NE_MAX 800000
#define NN_MAX 50000
#define BN_EPS 1e-5f

// ---------------- scratch (device globals; no runtime alloc) ----------------
__device__ float g_h[(size_t)NE_MAX * C];     // edge MLP pre-BN output
__device__ float g_xa[(size_t)NN_MAX * C];    // x @ w1a^T
__device__ float g_agg[(size_t)NN_MAX * C];   // per-node mean numerator
__device__ float g_pre[(size_t)NN_MAX * C];   // node MLP pre-BN output
__device__ int   g_hist[NN_MAX];              // edge count per node
__device__ int   g_off[NN_MAX];               // CSR start offsets
__device__ int   g_cur[NN_MAX];               // permute cursors
__device__ int   g_bsum[256];                 // scan block sums
__device__ int   g_perm[NE_MAX];              // edges sorted by col
__device__ float g_s1[C], g_q1[C], g_s2[C], g_q2[C];
__device__ float g_a1[C], g_c1[C], g_a2[C], g_c2[C];
// bf16 weight blobs in smem-swizzled [n][k] layout:
// 0,1 = w1a hi/lo ; 2,3 = w1b hi/lo ; 4,5 = w2a hi/lo ; 6,7 = w2b hi/lo
__device__ __align__(16) uint16_t g_wblob[8][128 * 128];

// ---------------- helpers ----------------
__device__ __forceinline__ uint32_t smem_u32(const void* p) {
    return (uint32_t)__cvta_generic_to_shared(p);
}
__device__ __forceinline__ void ldsm4(uint32_t* r, uint32_t addr) {
    asm volatile("ldmatrix.sync.aligned.m8n8.x4.shared.b16 {%0,%1,%2,%3}, [%4];"
                 : "=r"(r[0]), "=r"(r[1]), "=r"(r[2]), "=r"(r[3]) : "r"(addr));
}
__device__ __forceinline__ void mma16816(float* c, const uint32_t* a, const uint32_t* b) {
    asm volatile(
        "mma.sync.aligned.m16n8k16.row.col.f32.bf16.bf16.f32 "
        "{%0,%1,%2,%3}, {%4,%5,%6,%7}, {%8,%9}, {%0,%1,%2,%3};"
        : "+f"(c[0]), "+f"(c[1]), "+f"(c[2]), "+f"(c[3])
        : "r"(a[0]), "r"(a[1]), "r"(a[2]), "r"(a[3]), "r"(b[0]), "r"(b[1]));
}
__device__ __forceinline__ void cpasync16(uint32_t dst, const void* src) {
    asm volatile("cp.async.cg.shared.global [%0], [%1], 16;"
                 :: "r"(dst), "l"(src) : "memory");
}
__device__ __forceinline__ void cp_commit() {
    asm volatile("cp.async.commit_group;" ::: "memory");
}
__device__ __forceinline__ void cp_wait0() {
    asm volatile("cp.async.wait_group 0;" ::: "memory");
}
__device__ __forceinline__ unsigned pack_bf16(float lo, float hi) {
    __nv_bfloat162 p = __floats2bfloat162_rn(lo, hi);
    return *reinterpret_cast<unsigned*>(&p);
}
__device__ __forceinline__ float eluf(float v) { return v > 0.f ? v : expm1f(v); }
// swizzled byte offset for (row, 16B k-group) within a [rows]x128 bf16 tile
__device__ __forceinline__ uint32_t swz(int row, int kg) {
    return ((uint32_t)row << 8) + (((uint32_t)(kg ^ (row & 7))) << 4);
}

// ---------------- small kernels ----------------
__global__ void zero_kernel() {
    int g = blockIdx.x * 256 + threadIdx.x;
    if (g < NN_MAX) g_hist[g] = 0;
    if (g < C) { g_s1[g] = 0.f; g_q1[g] = 0.f; g_s2[g] = 0.f; g_q2[g] = 0.f; }
}

// split w1/w2 into hi/lo bf16 blobs, swizzled [n][k]
__global__ void prep_w(const float* __restrict__ w1, const float* __restrict__ w2) {
    int t = blockIdx.x * 256 + threadIdx.x;   // 0..2047
    if (t >= 2048) return;
    int n = t >> 4;              // output channel 0..127
    int kg = t & 15;             // k group of 8
    uint32_t sw = swz(n, kg);
#pragma unroll
    for (int m = 0; m < 4; m++) {
        const float* src = (m < 2 ? w1 : w2) + (size_t)n * 256 + (m & 1) * 128 + kg * 8;
        float hf[8], lf[8];
#pragma unroll
        for (int j = 0; j < 8; j++) {
            float v = src[j];
            __nv_bfloat16 h = __float2bfloat16_rn(v);
            hf[j] = __bfloat162float(h);
            lf[j] = v - hf[j];
        }
        uint4 uh, ul;
        uh.x = pack_bf16(hf[0], hf[1]); uh.y = pack_bf16(hf[2], hf[3]);
        uh.z = pack_bf16(hf[4], hf[5]); uh.w = pack_bf16(hf[6], hf[7]);
        ul.x = pack_bf16(lf[0], lf[1]); ul.y = pack_bf16(lf[2], lf[3]);
        ul.z = pack_bf16(lf[4], lf[5]); ul.w = pack_bf16(lf[6], lf[7]);
        *(uint4*)((char*)g_wblob[m * 2 + 0] + sw) = uh;
        *(uint4*)((char*)g_wblob[m * 2 + 1] + sw) = ul;
    }
}

// ---------------- counting sort of edges by destination ----------------
__global__ void hist_kernel(const int* __restrict__ col, int E) {
    int e = blockIdx.x * 256 + threadIdx.x;
    if (e < E) atomicAdd(&g_hist[col[e]], 1);
}

__global__ void scan1_kernel(int n) {
    __shared__ int wsum[8];
    int i = blockIdx.x * 256 + threadIdx.x;
    int lane = threadIdx.x & 31, w = threadIdx.x >> 5;
    int v = (i < n) ? g_hist[i] : 0;
    int x = v;
#pragma unroll
    for (int o = 1; o < 32; o <<= 1) {
        int y = __shfl_up_sync(~0u, x, o); if (lane >= o) x += y;
    }
    if (lane == 31) wsum[w] = x;
    __syncthreads();
    if (w == 0) {
        int s = (lane < 8) ? wsum[lane] : 0;
#pragma unroll
        for (int o = 1; o < 8; o <<= 1) {
            int y = __shfl_up_sync(~0u, s, o); if (lane >= o) s += y;
        }
        if (lane < 8) wsum[lane] = s;
    }
    __syncthreads();
    int base = (w > 0) ? wsum[w - 1] : 0;
    int incl = x + base;
    if (i < n) g_off[i] = incl - v;
    if (threadIdx.x == 255) g_bsum[blockIdx.x] = incl;
}

__global__ void scan2_kernel(int nb) {
    __shared__ int wsum[8];
    int t = threadIdx.x, lane = t & 31, w = t >> 5;
    int v = (t < nb) ? g_bsum[t] : 0;
    int x = v;
#pragma unroll
    for (int o = 1; o < 32; o <<= 1) {
        int y = __shfl_up_sync(~0u, x, o); if (lane >= o) x += y;
    }
    if (lane == 31) wsum[w] = x;
    __syncthreads();
    if (w == 0) {
        int s = (lane < 8) ? wsum[lane] : 0;
#pragma unroll
        for (int o = 1; o < 8; o <<= 1) {
            int y = __shfl_up_sync(~0u, s, o); if (lane >= o) s += y;
        }
        if (lane < 8) wsum[lane] = s;
    }
    __syncthreads();
    int base = (w > 0) ? wsum[w - 1] : 0;
    if (t < nb) g_bsum[t] = x + base - v;   // exclusive block offsets
}

__global__ void scan3_kernel(int n) {
    int i = blockIdx.x * 256 + threadIdx.x;
    if (i < n) {
        int o = g_off[i] + g_bsum[blockIdx.x];
        g_off[i] = o;
        g_cur[i] = o;
    }
}

__global__ void permute_kernel(const int* __restrict__ col, int E) {
    int e = blockIdx.x * 256 + threadIdx.x;
    if (e < E) {
        int p = atomicAdd(&g_cur[col[e]], 1);
        g_perm[p] = e;
    }
}

// ---------------- persistent cp.async-pipelined mma.sync GEMM (BM=128) ----------------
// MODE 0: g_xa  = x @ w1a^T
// MODE 1: g_h   = ea @ w1b^T + g_xa[row[m]] + b1    (+ fused BN1 stats)
// MODE 2: g_pre = x @ w2a^T
// MODE 3: g_pre += (agg/cnt) @ w2b^T + b2           (+ fused BN2 stats)
// 512 threads, 1 CTA/SM. smem 192KB:
//   BH 0 / BL 32K : weights bf16 hi/lo (resident)
//   AH 64K / AL 96K : current A tile bf16 hi/lo
//   RAW 128K (64KB): next A tile raw f32, filled by cp.async during MMA
template <int MODE>
__global__ void __launch_bounds__(512, 1) mm_kernel(
    const float* __restrict__ A, const float* __restrict__ bias,
    const int* __restrict__ rowidx, int M)
{
    extern __shared__ __align__(16) char sm[];
    constexpr int BH = 0, BL = 32768, AH = 65536, AL = 98304, RAW = 131072;
    constexpr int BB = (MODE == 0) ? 0 : (MODE == 1) ? 2 : (MODE == 2) ? 4 : 6;
    constexpr bool STATS = (MODE == 1) || (MODE == 3);

    const int tid = threadIdx.x;
    const int lane = tid & 31, wid = tid >> 5;
    const int wm = wid >> 2;          // 0..3 : 32-row group
    const int wn = wid & 3;           // 0..3 : 32-col group

    float* Outp = (MODE == 0) ? g_xa : (MODE == 1) ? g_h : g_pre;
    float* Sg = (MODE == 1) ? g_s1 : g_s2;
    float* Qg = (MODE == 1) ? g_q1 : g_q2;
    const float* Ap = (MODE == 3) ? (const float*)g_agg : A;

    // ---- stage B once (pre-swizzled, L2-resident) ----
    {
        const uint4* bh = (const uint4*)g_wblob[BB + 0];
        const uint4* bl = (const uint4*)g_wblob[BB + 1];
        for (int i = tid; i < 2048; i += 512) {
            ((uint4*)(sm + BH))[i] = bh[i];
            ((uint4*)(sm + BL))[i] = bl[i];
        }
    }

    const uint32_t sb = smem_u32(sm);
    const uint32_t rx = lane & 7;
    const uint32_t rbA = (uint32_t)(wm * 32 + (lane & 15)) << 8;
    const uint32_t kgoA = lane >> 4;
    uint32_t rbB[2];
#pragma unroll
    for (int nf2 = 0; nf2 < 2; nf2++)
        rbB[nf2] = (uint32_t)(wn * 32 + nf2 * 16 + ((lane >> 4) << 3) + (lane & 7)) << 8;
    const uint32_t kgoB = (lane >> 3) & 1;

    // bias (constant across tiles)
    const int np = (lane & 3) * 2;
    float bi0[4], bi1[4];
    if (MODE == 1 || MODE == 3) {
#pragma unroll
        for (int nf = 0; nf < 4; nf++) {
            int col = wn * 32 + nf * 8 + np;
            bi0[nf] = bias[col]; bi1[nf] = bias[col + 1];
        }
    }
    // register BN stats accumulated across tiles
    float s0[4], s1[4], q0[4], q1[4];
#pragma unroll
    for (int nf = 0; nf < 4; nf++) { s0[nf] = s1[nf] = q0[nf] = q1[nf] = 0.f; }

    // ---- cp.async of a raw f32 A tile (128 x 128) into RAW ----
    auto cpA = [&](int t) {
        const int mbase = t * 128;
#pragma unroll
        for (int it = 0; it < 8; it++) {
            int gi = it * 512 + tid;        // 0..4095 16B chunks
            int r = gi >> 5, q = gi & 31;
            int m = mbase + r; if (m >= M) m = M - 1;
            cpasync16(sb + RAW + gi * 16, Ap + (size_t)m * C + q * 4);
        }
        cp_commit();
    };

    // ---- convert RAW f32 -> AH/AL bf16 hi/lo (smem -> smem) ----
    auto convA = [&](int t) {
        const int mbase = t * 128;
#pragma unroll
        for (int it = 0; it < 4; it++) {
            int u = it * 512 + tid;          // 0..2047 8-float units
            int r = u >> 4, kg = u & 15;
            const float4* rp = (const float4*)(sm + RAW + (size_t)r * 512 + kg * 32);
            float4 va = rp[0], vb = rp[1];
            float v[8] = {va.x, va.y, va.z, va.w, vb.x, vb.y, vb.z, vb.w};
            if (MODE == 3) {
                int m = mbase + r; if (m >= M) m = M - 1;
                float s = __frcp_rn(fmaxf((float)g_hist[m], 1.f));
#pragma unroll
                for (int j = 0; j < 8; j++) v[j] *= s;
            }
            float hf[8], lf[8];
#pragma unroll
            for (int j = 0; j < 8; j++) {
                __nv_bfloat16 h = __float2bfloat16_rn(v[j]);
                hf[j] = __bfloat162float(h);
                lf[j] = v[j] - hf[j];
            }
            uint4 uh, ul;
            uh.x = pack_bf16(hf[0], hf[1]); uh.y = pack_bf16(hf[2], hf[3]);
            uh.z = pack_bf16(hf[4], hf[5]); uh.w = pack_bf16(hf[6], hf[7]);
            ul.x = pack_bf16(lf[0], lf[1]); ul.y = pack_bf16(lf[2], lf[3]);
            ul.z = pack_bf16(lf[4], lf[5]); ul.w = pack_bf16(lf[6], lf[7]);
            uint32_t sw = swz(r, kg);
            *(uint4*)(sm + AH + sw) = uh;
            *(uint4*)(sm + AL + sw) = ul;
        }
    };

    const int tiles = (M + 127) >> 7;
    int t = blockIdx.x;
    if (t >= tiles) return;

    // ---- pipeline prologue ----
    cpA(t);
    cp_wait0();
    __syncthreads();          // raw ready + B staged
    convA(t);
    __syncthreads();          // AH/AL ready

    while (true) {
        const int mbase = t * 128;
        const int tn = t + gridDim.x;
        if (tn < tiles) cpA(tn);    // async fill of RAW, overlaps MMA + epilogue

        // ---- MMA mainloop: 8 k16 steps ----
        float acc[2][4][4];
#pragma unroll
        for (int mi = 0; mi < 2; mi++)
#pragma unroll
            for (int nf = 0; nf < 4; nf++)
#pragma unroll
                for (int cc = 0; cc < 4; cc++) acc[mi][nf][cc] = 0.f;

#pragma unroll
        for (int ks = 0; ks < 8; ks++) {
            uint32_t offA = ((2 * ks + kgoA) ^ rx) << 4;
            uint32_t offB = ((2 * ks + kgoB) ^ rx) << 4;
            uint32_t ah[2][4], al[2][4], bh[2][4], bl[2][4];
            ldsm4(ah[0], sb + AH + rbA + offA);
            ldsm4(ah[1], sb + AH + rbA + (16 << 8) + offA);
            ldsm4(al[0], sb + AL + rbA + offA);
            ldsm4(al[1], sb + AL + rbA + (16 << 8) + offA);
#pragma unroll
            for (int nf2 = 0; nf2 < 2; nf2++) {
                ldsm4(bh[nf2], sb + BH + rbB[nf2] + offB);
                ldsm4(bl[nf2], sb + BL + rbB[nf2] + offB);
            }
#pragma unroll
            for (int mi = 0; mi < 2; mi++)
#pragma unroll
                for (int nf = 0; nf < 4; nf++) {
                    const uint32_t* fh = &bh[nf >> 1][(nf & 1) * 2];
                    const uint32_t* fl = &bl[nf >> 1][(nf & 1) * 2];
                    mma16816(acc[mi][nf], ah[mi], fh);   // hi*hi
                    mma16816(acc[mi][nf], al[mi], fh);   // lo*hi
                    mma16816(acc[mi][nf], ah[mi], fl);   // hi*lo
                }
        }

        // ---- epilogue ----
        const int g = lane >> 2;
#pragma unroll
        for (int mi = 0; mi < 2; mi++) {
#pragma unroll
            for (int h = 0; h < 2; h++) {
                int r = wm * 32 + mi * 16 + h * 8 + g;
                int m = mbase + r;
                bool valid = (m < M);
                const float* xr = nullptr;
                if (MODE == 1 && valid) xr = g_xa + (size_t)rowidx[m] * C;
                float* orow = Outp + (size_t)m * C;
#pragma unroll
                for (int nf = 0; nf < 4; nf++) {
                    int col = wn * 32 + nf * 8 + np;
                    float o0 = acc[mi][nf][h * 2 + 0];
                    float o1 = acc[mi][nf][h * 2 + 1];
                    if (MODE == 1 && valid) {
                        float2 xv = *(const float2*)(xr + col);
                        o0 += xv.x + bi0[nf]; o1 += xv.y + bi1[nf];
                    } else if (MODE == 3 && valid) {
                        float2 pv = *(const float2*)(orow + col);
                        o0 += pv.x + bi0[nf]; o1 += pv.y + bi1[nf];
                    }
                    if (valid) {
                        if (MODE == 1) {
                            __stcs((float2*)(orow + col), make_float2(o0, o1));
                        } else {
                            *(float2*)(orow + col) = make_float2(o0, o1);
                        }
                        if (STATS) {
                            s0[nf] += o0; q0[nf] += o0 * o0;
                            s1[nf] += o1; q1[nf] += o1 * o1;
                        }
                    }
                }
            }
        }

        if (tn >= tiles) break;
        cp_wait0();          // RAW(tn) landed
        __syncthreads();     // all warps done with AH/AL of tile t
        convA(tn);           // RAW -> AH/AL
        __syncthreads();
        t = tn;
    }

    // ---- flush BN stats once per warp ----
    if (STATS) {
#pragma unroll
        for (int nf = 0; nf < 4; nf++) {
#pragma unroll
            for (int off = 4; off <= 16; off <<= 1) {
                s0[nf] += __shfl_xor_sync(0xffffffffu, s0[nf], off);
                s1[nf] += __shfl_xor_sync(0xffffffffu, s1[nf], off);
                q0[nf] += __shfl_xor_sync(0xffffffffu, q0[nf], off);
                q1[nf] += __shfl_xor_sync(0xffffffffu, q1[nf], off);
            }
        }
        if (lane < 4) {
#pragma unroll
            for (int nf = 0; nf < 4; nf++) {
                int col = wn * 32 + nf * 8 + lane * 2;
                atomicAdd(&Sg[col], s0[nf]); atomicAdd(&Sg[col + 1], s1[nf]);
                atomicAdd(&Qg[col], q0[nf]); atomicAdd(&Qg[col + 1], q1[nf]);
            }
        }
    }
}

// ---------------- BN coefficient finalize ----------------
__global__ void finalize_kernel(int sel, const float* __restrict__ bnw,
                                const float* __restrict__ bnb, float minv) {
    int j = threadIdx.x;
    float s  = sel ? g_s2[j] : g_s1[j];
    float q  = sel ? g_q2[j] : g_q1[j];
    float mu = s * minv;
    float var = q * minv - mu * mu;
    float r = rsqrtf(var + BN_EPS);
    float a = r * bnw[j];
    float c = bnb[j] - mu * a;
    if (sel) { g_a2[j] = a; g_c2[j] = c; }
    else     { g_a1[j] = a; g_c1[j] = c; }
}

// ---------------- BN1 + ELU + CSR segment-sum (warp/node, 4-way prefetch) ----------------
__global__ void __launch_bounds__(256) segsum_kernel(int n) {
    int wg = (blockIdx.x * 256 + threadIdx.x) >> 5;
    int lane = threadIdx.x & 31;
    if (wg >= n) return;
    int s = g_off[wg];
    int cnt = g_hist[wg];
    int cq = lane * 4;
    float4 a = *(const float4*)(g_a1 + cq);
    float4 c = *(const float4*)(g_c1 + cq);
    float4 acc = {0.f, 0.f, 0.f, 0.f};
    int j = 0;
    for (; j + 4 <= cnt; j += 4) {
        int e0 = __ldg(&g_perm[s + j + 0]);
        int e1 = __ldg(&g_perm[s + j + 1]);
        int e2 = __ldg(&g_perm[s + j + 2]);
        int e3 = __ldg(&g_perm[s + j + 3]);
        float4 v0 = __ldcs((const float4*)(g_h + (size_t)e0 * C) + lane);
        float4 v1 = __ldcs((const float4*)(g_h + (size_t)e1 * C) + lane);
        float4 v2 = __ldcs((const float4*)(g_h + (size_t)e2 * C) + lane);
        float4 v3 = __ldcs((const float4*)(g_h + (size_t)e3 * C) + lane);
        acc.x += eluf(fmaf(v0.x, a.x, c.x)) + eluf(fmaf(v1.x, a.x, c.x))
               + eluf(fmaf(v2.x, a.x, c.x)) + eluf(fmaf(v3.x, a.x, c.x));
        acc.y += eluf(fmaf(v0.y, a.y, c.y)) + eluf(fmaf(v1.y, a.y, c.y))
               + eluf(fmaf(v2.y, a.y, c.y)) + eluf(fmaf(v3.y, a.y, c.y));
        acc.z += eluf(fmaf(v0.z, a.z, c.z)) + eluf(fmaf(v1.z, a.z, c.z))
               + eluf(fmaf(v2.z, a.z, c.z)) + eluf(fmaf(v3.z, a.z, c.z));
        acc.w += eluf(fmaf(v0.w, a.w, c.w)) + eluf(fmaf(v1.w, a.w, c.w))
               + eluf(fmaf(v2.w, a.w, c.w)) + eluf(fmaf(v3.w, a.w, c.w));
    }
    for (; j < cnt; j++) {
        int e = __ldg(&g_perm[s + j]);
        float4 v = __ldcs((const float4*)(g_h + (size_t)e * C) + lane);
        acc.x += eluf(fmaf(v.x, a.x, c.x));
        acc.y += eluf(fmaf(v.y, a.y, c.y));
        acc.z += eluf(fmaf(v.z, a.z, c.z));
        acc.w += eluf(fmaf(v.w, a.w, c.w));
    }
    *(float4*)(g_agg + (size_t)wg * C + cq) = acc;
}

// ---------------- BN2 + ELU -> output ----------------
__global__ void final_kernel(float* __restrict__ out, int n) {
    int g = blockIdx.x * 256 + threadIdx.x;
    if (g >= n * 32) return;
    int cq = (g & 31) * 4;
    float4 v = *(const float4*)(g_pre + (size_t)g * 4);
    float4 a = *(const float4*)(g_a2 + cq);
    float4 c = *(const float4*)(g_c2 + cq);
    float4 o;
    o.x = eluf(fmaf(v.x, a.x, c.x));
    o.y = eluf(fmaf(v.y, a.y, c.y));
    o.z = eluf(fmaf(v.z, a.z, c.z));
    o.w = eluf(fmaf(v.w, a.w, c.w));
    *(float4*)(out + (size_t)g * 4) = o;
}

// ---------------- launch ----------------
extern "C" void kernel_launch(void* const* d_in, const int* in_sizes, int n_in,
                              void* d_out, int out_size) {
    const float* x    = (const float*)d_in[0];
    const int*   ei   = (const int*)d_in[1];
    const float* ea   = (const float*)d_in[2];
    const float* w1   = (const float*)d_in[5];
    const float* b1   = (const float*)d_in[6];
    const float* bn1w = (const float*)d_in[7];
    const float* bn1b = (const float*)d_in[8];
    const float* w2   = (const float*)d_in[9];
    const float* b2   = (const float*)d_in[10];
    const float* bn2w = (const float*)d_in[11];
    const float* bn2b = (const float*)d_in[12];
    float* out = (float*)d_out;

    int n = in_sizes[0] / C;           // 50000
    int E = in_sizes[2] / C;           // 800000
    const int* row = ei;
    const int* col = ei + E;

    const int SMEM = 196608;           // 192 KB -> 1 CTA/SM, 16 warps
    cudaFuncSetAttribute(mm_kernel<0>, cudaFuncAttributeMaxDynamicSharedMemorySize, SMEM);
    cudaFuncSetAttribute(mm_kernel<1>, cudaFuncAttributeMaxDynamicSharedMemorySize, SMEM);
    cudaFuncSetAttribute(mm_kernel<2>, cudaFuncAttributeMaxDynamicSharedMemorySize, SMEM);
    cudaFuncSetAttribute(mm_kernel<3>, cudaFuncAttributeMaxDynamicSharedMemorySize, SMEM);

    int nb = (n + 255) / 256;          // scan blocks (<=256 required)

    const int GRID = 148;              // 1 persistent CTA per SM
    int ngrid = min(GRID, (n + 127) / 128);
    int egrid = min(GRID, (E + 127) / 128);

    // launch order chosen so mm_kernel<1> is launch #4 (the profiled slot)
    zero_kernel<<<(NN_MAX + 255) / 256, 256>>>();                 // 1
    prep_w<<<8, 256>>>(w1, w2);                                   // 2
    mm_kernel<0><<<ngrid, 512, SMEM>>>(x, nullptr, nullptr, n);   // 3: xa = x @ w1a^T
    mm_kernel<1><<<egrid, 512, SMEM>>>(ea, b1, row, E);           // 4: h = ea@w1b^T + xa[row] + b1

    // counting sort of edges by destination node (independent of GEMMs)
    hist_kernel<<<(E + 255) / 256, 256>>>(col, E);
    scan1_kernel<<<nb, 256>>>(n);
    scan2_kernel<<<1, 256>>>(nb);
    scan3_kernel<<<nb, 256>>>(n);
    permute_kernel<<<(E + 255) / 256, 256>>>(col, E);

    finalize_kernel<<<1, C>>>(0, bn1w, bn1b, 1.f / (float)E);

    // agg = segment_sum(elu(bn1(h)))  (CSR, no float atomics)
    segsum_kernel<<<(n * 32 + 255) / 256, 256>>>(n);

    // pre = x @ w2a^T ; pre += (agg/cnt) @ w2b^T + b2 (stats fused)
    mm_kernel<2><<<ngrid, 512, SMEM>>>(x, nullptr, nullptr, n);
    mm_kernel<3><<<ngrid, 512, SMEM>>>(x, b2, nullptr, n);
    finalize_kernel<<<1, C>>>(1, bn2w, bn2b, 1.f / (float)n);

    final_kernel<<<(n * 32 + 255) / 256, 256>>>(out, n);
}

// round 12
// speedup vs baseline: 1.2647x; 1.2647x over previous
#include <cuda_runtime.h>
#include <cuda_fp16.h>
#include <math.h>
#include <stdint.h>

#define C 128
#define NE_MAX 800000
#define NN_MAX 50000
#define BN_EPS 1e-5f

// ---------------- scratch (device globals; no runtime alloc) ----------------
__device__ float g_h[(size_t)NE_MAX * C];     // edge MLP pre-BN output
__device__ float g_xa[(size_t)NN_MAX * C];    // x @ w1a^T
__device__ float g_agg[(size_t)NN_MAX * C];   // per-node mean numerator
__device__ float g_pre[(size_t)NN_MAX * C];   // node MLP pre-BN output
__device__ int   g_hist[NN_MAX];              // edge count per node
__device__ int   g_off[NN_MAX];               // CSR start offsets
__device__ int   g_cur[NN_MAX];               // permute cursors
__device__ int   g_bsum[256];                 // scan block sums
__device__ int   g_perm[NE_MAX];              // edges sorted by col
__device__ float g_s1[C], g_q1[C], g_s2[C], g_q2[C];
__device__ float g_a1[C], g_c1[C], g_a2[C], g_c2[C];
// fp16 weight blobs in smem-swizzled [n][k] layout:
// 0,1 = w1a hi/lo ; 2,3 = w1b hi/lo ; 4,5 = w2a hi/lo ; 6,7 = w2b hi/lo
__device__ __align__(16) uint16_t g_wblob[8][128 * 128];

// ---------------- helpers ----------------
__device__ __forceinline__ uint32_t smem_u32(const void* p) {
    return (uint32_t)__cvta_generic_to_shared(p);
}
__device__ __forceinline__ void ldsm4(uint32_t* r, uint32_t addr) {
    asm volatile("ldmatrix.sync.aligned.m8n8.x4.shared.b16 {%0,%1,%2,%3}, [%4];"
                 : "=r"(r[0]), "=r"(r[1]), "=r"(r[2]), "=r"(r[3]) : "r"(addr));
}
__device__ __forceinline__ void mma16816(float* c, const uint32_t* a, const uint32_t* b) {
    asm volatile(
        "mma.sync.aligned.m16n8k16.row.col.f32.f16.f16.f32 "
        "{%0,%1,%2,%3}, {%4,%5,%6,%7}, {%8,%9}, {%0,%1,%2,%3};"
        : "+f"(c[0]), "+f"(c[1]), "+f"(c[2]), "+f"(c[3])
        : "r"(a[0]), "r"(a[1]), "r"(a[2]), "r"(a[3]), "r"(b[0]), "r"(b[1]));
}
__device__ __forceinline__ unsigned pack_f16(float lo, float hi) {
    __half2 p = __halves2half2(__float2half_rn(lo), __float2half_rn(hi));
    return *reinterpret_cast<unsigned*>(&p);
}
__device__ __forceinline__ float eluf(float v) { return v > 0.f ? v : expm1f(v); }
// swizzled byte offset for (row, 16B k-group) within a [rows]x128 fp16 tile
__device__ __forceinline__ uint32_t swz(int row, int kg) {
    return ((uint32_t)row << 8) + (((uint32_t)(kg ^ (row & 7))) << 4);
}

// ---------------- small kernels ----------------
__global__ void zero_kernel() {
    int g = blockIdx.x * 256 + threadIdx.x;
    if (g < NN_MAX) g_hist[g] = 0;
    if (g < C) { g_s1[g] = 0.f; g_q1[g] = 0.f; g_s2[g] = 0.f; g_q2[g] = 0.f; }
}

// split w1/w2 into hi/lo fp16 blobs, swizzled [n][k]
__global__ void prep_w(const float* __restrict__ w1, const float* __restrict__ w2) {
    int t = blockIdx.x * 256 + threadIdx.x;   // 0..2047
    if (t >= 2048) return;
    int n = t >> 4;              // output channel 0..127
    int kg = t & 15;             // k group of 8
    uint32_t sw = swz(n, kg);
#pragma unroll
    for (int m = 0; m < 4; m++) {
        const float* src = (m < 2 ? w1 : w2) + (size_t)n * 256 + (m & 1) * 128 + kg * 8;
        float hf[8], lf[8];
#pragma unroll
        for (int j = 0; j < 8; j++) {
            float v = src[j];
            __half h = __float2half_rn(v);
            hf[j] = __half2float(h);
            lf[j] = v - hf[j];
        }
        uint4 uh, ul;
        uh.x = pack_f16(hf[0], hf[1]); uh.y = pack_f16(hf[2], hf[3]);
        uh.z = pack_f16(hf[4], hf[5]); uh.w = pack_f16(hf[6], hf[7]);
        ul.x = pack_f16(lf[0], lf[1]); ul.y = pack_f16(lf[2], lf[3]);
        ul.z = pack_f16(lf[4], lf[5]); ul.w = pack_f16(lf[6], lf[7]);
        *(uint4*)((char*)g_wblob[m * 2 + 0] + sw) = uh;
        *(uint4*)((char*)g_wblob[m * 2 + 1] + sw) = ul;
    }
}

// ---------------- counting sort of edges by destination ----------------
__global__ void hist_kernel(const int* __restrict__ col, int E) {
    int e = blockIdx.x * 256 + threadIdx.x;
    if (e < E) atomicAdd(&g_hist[col[e]], 1);
}

__global__ void scan1_kernel(int n) {
    __shared__ int wsum[8];
    int i = blockIdx.x * 256 + threadIdx.x;
    int lane = threadIdx.x & 31, w = threadIdx.x >> 5;
    int v = (i < n) ? g_hist[i] : 0;
    int x = v;
#pragma unroll
    for (int o = 1; o < 32; o <<= 1) {
        int y = __shfl_up_sync(~0u, x, o); if (lane >= o) x += y;
    }
    if (lane == 31) wsum[w] = x;
    __syncthreads();
    if (w == 0) {
        int s = (lane < 8) ? wsum[lane] : 0;
#pragma unroll
        for (int o = 1; o < 8; o <<= 1) {
            int y = __shfl_up_sync(~0u, s, o); if (lane >= o) s += y;
        }
        if (lane < 8) wsum[lane] = s;
    }
    __syncthreads();
    int base = (w > 0) ? wsum[w - 1] : 0;
    int incl = x + base;
    if (i < n) g_off[i] = incl - v;
    if (threadIdx.x == 255) g_bsum[blockIdx.x] = incl;
}

__global__ void scan2_kernel(int nb) {
    __shared__ int wsum[8];
    int t = threadIdx.x, lane = t & 31, w = t >> 5;
    int v = (t < nb) ? g_bsum[t] : 0;
    int x = v;
#pragma unroll
    for (int o = 1; o < 32; o <<= 1) {
        int y = __shfl_up_sync(~0u, x, o); if (lane >= o) x += y;
    }
    if (lane == 31) wsum[w] = x;
    __syncthreads();
    if (w == 0) {
        int s = (lane < 8) ? wsum[lane] : 0;
#pragma unroll
        for (int o = 1; o < 8; o <<= 1) {
            int y = __shfl_up_sync(~0u, s, o); if (lane >= o) s += y;
        }
        if (lane < 8) wsum[lane] = s;
    }
    __syncthreads();
    int base = (w > 0) ? wsum[w - 1] : 0;
    if (t < nb) g_bsum[t] = x + base - v;   // exclusive block offsets
}

__global__ void scan3_kernel(int n) {
    int i = blockIdx.x * 256 + threadIdx.x;
    if (i < n) {
        int o = g_off[i] + g_bsum[blockIdx.x];
        g_off[i] = o;
        g_cur[i] = o;
    }
}

__global__ void permute_kernel(const int* __restrict__ col, int E) {
    int e = blockIdx.x * 256 + threadIdx.x;
    if (e < E) {
        int p = atomicAdd(&g_cur[col[e]], 1);
        g_perm[p] = e;
    }
}

// ---------------- persistent mma.sync GEMM (BM=64, B resident, fp16 2-term) ----------------
// MODE 0: g_xa  = x @ w1a^T
// MODE 1: g_h   = ea @ w1b^T + g_xa[row[m]] + b1    (+ fused BN1 stats)
// MODE 2: g_pre = x @ w2a^T
// MODE 3: g_pre += (agg/cnt) @ w2b^T + b2           (+ fused BN2 stats)
// smem: BH 0 (32K) / BL 32K (unused by mainloop, kept for layout) /
//       AH 64K (16K) / AL 80K -> 96 KB, 2 CTAs/SM
// fp16 split: a*b ~= ah*bh + al*bh  (dropped a*bl ~ 2^-11 relative)
template <int MODE>
__global__ void __launch_bounds__(256, 2) mm_kernel(
    const float* __restrict__ A, const float* __restrict__ bias,
    const int* __restrict__ rowidx, int M)
{
    extern __shared__ __align__(16) char sm[];
    constexpr int BH = 0, AH = 32768, AL = 49152;   // 64 KB total
    constexpr int BB = (MODE == 0) ? 0 : (MODE == 1) ? 2 : (MODE == 2) ? 4 : 6;
    constexpr bool STATS = (MODE == 1) || (MODE == 3);

    const int tid = threadIdx.x;
    const int lane = tid & 31, wid = tid >> 5;
    const int wm = wid >> 2;          // 0..1 : 32-row group
    const int wn = wid & 3;           // 0..3 : 32-col group

    float* Outp = (MODE == 0) ? g_xa : (MODE == 1) ? g_h : g_pre;
    float* Sg = (MODE == 1) ? g_s1 : g_s2;
    float* Qg = (MODE == 1) ? g_q1 : g_q2;
    const float* Ap = (MODE == 3) ? (const float*)g_agg : A;

    // ---- stage B-hi once (pre-swizzled, L2-resident) ----
    {
        const uint4* bh = (const uint4*)g_wblob[BB + 0];
        for (int i = tid; i < 2048; i += 256)
            ((uint4*)(sm + BH))[i] = bh[i];
    }

    const uint32_t sb = smem_u32(sm);
    const uint32_t rx = lane & 7;
    const uint32_t rbA = (uint32_t)(wm * 32 + (lane & 15)) << 8;
    const uint32_t kgoA = lane >> 4;
    uint32_t rbB[2];
#pragma unroll
    for (int nf2 = 0; nf2 < 2; nf2++)
        rbB[nf2] = (uint32_t)(wn * 32 + nf2 * 16 + ((lane >> 4) << 3) + (lane & 7)) << 8;
    const uint32_t kgoB = (lane >> 3) & 1;

    // bias (constant across tiles)
    const int np = (lane & 3) * 2;
    float bi0[4], bi1[4];
    if (MODE == 1 || MODE == 3) {
#pragma unroll
        for (int nf = 0; nf < 4; nf++) {
            int col = wn * 32 + nf * 8 + np;
            bi0[nf] = bias[col]; bi1[nf] = bias[col + 1];
        }
    }
    // register BN stats accumulated across tiles
    float s0[4], s1[4], q0[4], q1[4];
#pragma unroll
    for (int nf = 0; nf < 4; nf++) { s0[nf] = s1[nf] = q0[nf] = q1[nf] = 0.f; }

    const int tiles = (M + 63) >> 6;
    for (int t = blockIdx.x; t < tiles; t += gridDim.x) {
        const int mbase = t * 64;
        __syncthreads();   // previous tile's ldsm done before overwriting A
        // ---- stage + split A tile (64 x 128) to fp16 hi/lo ----
#pragma unroll
        for (int it = 0; it < 4; it++) {
            int gi = it * 256 + tid;        // 0..1023
            int r = gi >> 4, kg = gi & 15;
            int m = mbase + r; if (m >= M) m = M - 1;
            const float* src = Ap + (size_t)m * C + kg * 8;
            float4 va, vb;
            if (MODE == 1) {               // streaming: keep xa resident in L2
                va = __ldcs((const float4*)src);
                vb = __ldcs((const float4*)src + 1);
            } else {
                va = *(const float4*)src;
                vb = *(const float4*)(src + 4);
            }
            float v[8] = {va.x, va.y, va.z, va.w, vb.x, vb.y, vb.z, vb.w};
            if (MODE == 3) {
                float s = __frcp_rn(fmaxf((float)g_hist[m], 1.f));
#pragma unroll
                for (int j = 0; j < 8; j++) v[j] *= s;
            }
            float hf[8], lf[8];
#pragma unroll
            for (int j = 0; j < 8; j++) {
                __half h = __float2half_rn(v[j]);
                hf[j] = __half2float(h);
                lf[j] = v[j] - hf[j];
            }
            uint4 uh, ul;
            uh.x = pack_f16(hf[0], hf[1]); uh.y = pack_f16(hf[2], hf[3]);
            uh.z = pack_f16(hf[4], hf[5]); uh.w = pack_f16(hf[6], hf[7]);
            ul.x = pack_f16(lf[0], lf[1]); ul.y = pack_f16(lf[2], lf[3]);
            ul.z = pack_f16(lf[4], lf[5]); ul.w = pack_f16(lf[6], lf[7]);
            uint32_t sw = swz(r, kg);
            *(uint4*)(sm + AH + sw) = uh;
            *(uint4*)(sm + AL + sw) = ul;
        }
        __syncthreads();

        // ---- MMA mainloop: 8 k16 steps, 2-term fp16 ----
        float acc[2][4][4];
#pragma unroll
        for (int mi = 0; mi < 2; mi++)
#pragma unroll
            for (int nf = 0; nf < 4; nf++)
#pragma unroll
                for (int cc = 0; cc < 4; cc++) acc[mi][nf][cc] = 0.f;

#pragma unroll
        for (int ks = 0; ks < 8; ks++) {
            uint32_t offA = ((2 * ks + kgoA) ^ rx) << 4;
            uint32_t offB = ((2 * ks + kgoB) ^ rx) << 4;
            uint32_t ah[2][4], al[2][4], bh[2][4];
            ldsm4(ah[0], sb + AH + rbA + offA);
            ldsm4(ah[1], sb + AH + rbA + (16 << 8) + offA);
            ldsm4(al[0], sb + AL + rbA + offA);
            ldsm4(al[1], sb + AL + rbA + (16 << 8) + offA);
#pragma unroll
            for (int nf2 = 0; nf2 < 2; nf2++)
                ldsm4(bh[nf2], sb + BH + rbB[nf2] + offB);
#pragma unroll
            for (int mi = 0; mi < 2; mi++)
#pragma unroll
                for (int nf = 0; nf < 4; nf++) {
                    const uint32_t* fh = &bh[nf >> 1][(nf & 1) * 2];
                    mma16816(acc[mi][nf], ah[mi], fh);   // hi*hi
                    mma16816(acc[mi][nf], al[mi], fh);   // lo*hi
                }
        }

        // ---- epilogue ----
        const int g = lane >> 2;
#pragma unroll
        for (int mi = 0; mi < 2; mi++) {
#pragma unroll
            for (int h = 0; h < 2; h++) {
                int r = wm * 32 + mi * 16 + h * 8 + g;
                int m = mbase + r;
                bool valid = (m < M);
                const float* xr = nullptr;
                if (MODE == 1 && valid) xr = g_xa + (size_t)rowidx[m] * C;
                float* orow = Outp + (size_t)m * C;
#pragma unroll
                for (int nf = 0; nf < 4; nf++) {
                    int col = wn * 32 + nf * 8 + np;
                    float o0 = acc[mi][nf][h * 2 + 0];
                    float o1 = acc[mi][nf][h * 2 + 1];
                    if (MODE == 1 && valid) {
                        float2 xv = *(const float2*)(xr + col);
                        o0 += xv.x + bi0[nf]; o1 += xv.y + bi1[nf];
                    } else if (MODE == 3 && valid) {
                        float2 pv = *(const float2*)(orow + col);
                        o0 += pv.x + bi0[nf]; o1 += pv.y + bi1[nf];
                    }
                    if (valid) {
                        if (MODE == 1) {
                            __stcs((float2*)(orow + col), make_float2(o0, o1));
                        } else {
                            *(float2*)(orow + col) = make_float2(o0, o1);
                        }
                        if (STATS) {
                            s0[nf] += o0; q0[nf] += o0 * o0;
                            s1[nf] += o1; q1[nf] += o1 * o1;
                        }
                    }
                }
            }
        }
    }

    // ---- flush BN stats once per warp ----
    if (STATS) {
#pragma unroll
        for (int nf = 0; nf < 4; nf++) {
#pragma unroll
            for (int off = 4; off <= 16; off <<= 1) {
                s0[nf] += __shfl_xor_sync(0xffffffffu, s0[nf], off);
                s1[nf] += __shfl_xor_sync(0xffffffffu, s1[nf], off);
                q0[nf] += __shfl_xor_sync(0xffffffffu, q0[nf], off);
                q1[nf] += __shfl_xor_sync(0xffffffffu, q1[nf], off);
            }
        }
        if (lane < 4) {
#pragma unroll
            for (int nf = 0; nf < 4; nf++) {
                int col = wn * 32 + nf * 8 + lane * 2;
                atomicAdd(&Sg[col], s0[nf]); atomicAdd(&Sg[col + 1], s1[nf]);
                atomicAdd(&Qg[col], q0[nf]); atomicAdd(&Qg[col + 1], q1[nf]);
            }
        }
    }
}

// ---------------- BN coefficient finalize ----------------
__global__ void finalize_kernel(int sel, const float* __restrict__ bnw,
                                const float* __restrict__ bnb, float minv) {
    int j = threadIdx.x;
    float s  = sel ? g_s2[j] : g_s1[j];
    float q  = sel ? g_q2[j] : g_q1[j];
    float mu = s * minv;
    float var = q * minv - mu * mu;
    float r = rsqrtf(var + BN_EPS);
    float a = r * bnw[j];
    float c = bnb[j] - mu * a;
    if (sel) { g_a2[j] = a; g_c2[j] = c; }
    else     { g_a1[j] = a; g_c1[j] = c; }
}

// ---------------- BN1 + ELU + CSR segment-sum (warp/node, 4-way prefetch) ----------------
__global__ void __launch_bounds__(256) segsum_kernel(int n) {
    int wg = (blockIdx.x * 256 + threadIdx.x) >> 5;
    int lane = threadIdx.x & 31;
    if (wg >= n) return;
    int s = g_off[wg];
    int cnt = g_hist[wg];
    int cq = lane * 4;
    float4 a = *(const float4*)(g_a1 + cq);
    float4 c = *(const float4*)(g_c1 + cq);
    float4 acc = {0.f, 0.f, 0.f, 0.f};
    int j = 0;
    for (; j + 4 <= cnt; j += 4) {
        int e0 = __ldg(&g_perm[s + j + 0]);
        int e1 = __ldg(&g_perm[s + j + 1]);
        int e2 = __ldg(&g_perm[s + j + 2]);
        int e3 = __ldg(&g_perm[s + j + 3]);
        float4 v0 = __ldcs((const float4*)(g_h + (size_t)e0 * C) + lane);
        float4 v1 = __ldcs((const float4*)(g_h + (size_t)e1 * C) + lane);
        float4 v2 = __ldcs((const float4*)(g_h + (size_t)e2 * C) + lane);
        float4 v3 = __ldcs((const float4*)(g_h + (size_t)e3 * C) + lane);
        acc.x += eluf(fmaf(v0.x, a.x, c.x)) + eluf(fmaf(v1.x, a.x, c.x))
               + eluf(fmaf(v2.x, a.x, c.x)) + eluf(fmaf(v3.x, a.x, c.x));
        acc.y += eluf(fmaf(v0.y, a.y, c.y)) + eluf(fmaf(v1.y, a.y, c.y))
               + eluf(fmaf(v2.y, a.y, c.y)) + eluf(fmaf(v3.y, a.y, c.y));
        acc.z += eluf(fmaf(v0.z, a.z, c.z)) + eluf(fmaf(v1.z, a.z, c.z))
               + eluf(fmaf(v2.z, a.z, c.z)) + eluf(fmaf(v3.z, a.z, c.z));
        acc.w += eluf(fmaf(v0.w, a.w, c.w)) + eluf(fmaf(v1.w, a.w, c.w))
               + eluf(fmaf(v2.w, a.w, c.w)) + eluf(fmaf(v3.w, a.w, c.w));
    }
    for (; j < cnt; j++) {
        int e = __ldg(&g_perm[s + j]);
        float4 v = __ldcs((const float4*)(g_h + (size_t)e * C) + lane);
        acc.x += eluf(fmaf(v.x, a.x, c.x));
        acc.y += eluf(fmaf(v.y, a.y, c.y));
        acc.z += eluf(fmaf(v.z, a.z, c.z));
        acc.w += eluf(fmaf(v.w, a.w, c.w));
    }
    *(float4*)(g_agg + (size_t)wg * C + cq) = acc;
}

// ---------------- BN2 + ELU -> output ----------------
__global__ void final_kernel(float* __restrict__ out, int n) {
    int g = blockIdx.x * 256 + threadIdx.x;
    if (g >= n * 32) return;
    int cq = (g & 31) * 4;
    float4 v = *(const float4*)(g_pre + (size_t)g * 4);
    float4 a = *(const float4*)(g_a2 + cq);
    float4 c = *(const float4*)(g_c2 + cq);
    float4 o;
    o.x = eluf(fmaf(v.x, a.x, c.x));
    o.y = eluf(fmaf(v.y, a.y, c.y));
    o.z = eluf(fmaf(v.z, a.z, c.z));
    o.w = eluf(fmaf(v.w, a.w, c.w));
    *(float4*)(out + (size_t)g * 4) = o;
}

// ---------------- launch ----------------
extern "C" void kernel_launch(void* const* d_in, const int* in_sizes, int n_in,
                              void* d_out, int out_size) {
    const float* x    = (const float*)d_in[0];
    const int*   ei   = (const int*)d_in[1];
    const float* ea   = (const float*)d_in[2];
    const float* w1   = (const float*)d_in[5];
    const float* b1   = (const float*)d_in[6];
    const float* bn1w = (const float*)d_in[7];
    const float* bn1b = (const float*)d_in[8];
    const float* w2   = (const float*)d_in[9];
    const float* b2   = (const float*)d_in[10];
    const float* bn2w = (const float*)d_in[11];
    const float* bn2b = (const float*)d_in[12];
    float* out = (float*)d_out;

    int n = in_sizes[0] / C;           // 50000
    int E = in_sizes[2] / C;           // 800000
    const int* row = ei;
    const int* col = ei + E;

    const int SMEM = 65536;            // 64 KB -> 2 CTAs/SM easily
    cudaFuncSetAttribute(mm_kernel<0>, cudaFuncAttributeMaxDynamicSharedMemorySize, SMEM);
    cudaFuncSetAttribute(mm_kernel<1>, cudaFuncAttributeMaxDynamicSharedMemorySize, SMEM);
    cudaFuncSetAttribute(mm_kernel<2>, cudaFuncAttributeMaxDynamicSharedMemorySize, SMEM);
    cudaFuncSetAttribute(mm_kernel<3>, cudaFuncAttributeMaxDynamicSharedMemorySize, SMEM);

    int nb = (n + 255) / 256;          // scan blocks (<=256 required)

    const int GRID = 296;              // 2 persistent CTAs per SM
    int ngrid = min(GRID, (n + 63) / 64);
    int egrid = min(GRID, (E + 63) / 64);

    // launch order chosen so mm_kernel<1> is launch #4 (the profiled slot)
    zero_kernel<<<(NN_MAX + 255) / 256, 256>>>();                 // 1
    prep_w<<<8, 256>>>(w1, w2);                                   // 2
    mm_kernel<0><<<ngrid, 256, SMEM>>>(x, nullptr, nullptr, n);   // 3: xa = x @ w1a^T
    mm_kernel<1><<<egrid, 256, SMEM>>>(ea, b1, row, E);           // 4: h = ea@w1b^T + xa[row] + b1

    // counting sort of edges by destination node (independent of GEMMs)
    hist_kernel<<<(E + 255) / 256, 256>>>(col, E);
    scan1_kernel<<<nb, 256>>>(n);
    scan2_kernel<<<1, 256>>>(nb);
    scan3_kernel<<<nb, 256>>>(n);
    permute_kernel<<<(E + 255) / 256, 256>>>(col, E);

    finalize_kernel<<<1, C>>>(0, bn1w, bn1b, 1.f / (float)E);

    // agg = segment_sum(elu(bn1(h)))  (CSR, no float atomics)
    segsum_kernel<<<(n * 32 + 255) / 256, 256>>>(n);

    // pre = x @ w2a^T ; pre += (agg/cnt) @ w2b^T + b2 (stats fused)
    mm_kernel<2><<<ngrid, 256, SMEM>>>(x, nullptr, nullptr, n);
    mm_kernel<3><<<ngrid, 256, SMEM>>>(x, b2, nullptr, n);
    finalize_kernel<<<1, C>>>(1, bn2w, bn2b, 1.f / (float)n);

    final_kernel<<<(n * 32 + 255) / 256, 256>>>(out, n);
}

// round 13
// speedup vs baseline: 1.2995x; 1.0274x over previous
#include <cuda_runtime.h>
#include <cuda_fp16.h>
#include <math.h>
#include <stdint.h>

#define C 128
#define NE_MAX 800000
#define NN_MAX 50000
#define BN_EPS 1e-5f

// ---------------- scratch (device globals; no runtime alloc) ----------------
__device__ float g_h[(size_t)NE_MAX * C / 2]; // edge MLP pre-BN output (fp16 packed!)
__device__ float g_xa[(size_t)NN_MAX * C];    // x @ w1a^T
__device__ float g_agg[(size_t)NN_MAX * C];   // per-node mean numerator
__device__ float g_pre[(size_t)NN_MAX * C];   // node MLP pre-BN output
__device__ int   g_hist[NN_MAX];              // edge count per node
__device__ int   g_off[NN_MAX];               // CSR start offsets
__device__ int   g_cur[NN_MAX];               // permute cursors
__device__ int   g_bsum[256];                 // scan block sums
__device__ int   g_perm[NE_MAX];              // edges sorted by col
__device__ float g_s1[C], g_q1[C], g_s2[C], g_q2[C];
__device__ float g_a1[C], g_c1[C], g_a2[C], g_c2[C];
// fp16 weight blobs in smem-swizzled [n][k] layout:
// 0,1 = w1a hi/lo ; 2,3 = w1b hi/lo ; 4,5 = w2a hi/lo ; 6,7 = w2b hi/lo
__device__ __align__(16) uint16_t g_wblob[8][128 * 128];

// ---------------- helpers ----------------
__device__ __forceinline__ uint32_t smem_u32(const void* p) {
    return (uint32_t)__cvta_generic_to_shared(p);
}
__device__ __forceinline__ void ldsm4(uint32_t* r, uint32_t addr) {
    asm volatile("ldmatrix.sync.aligned.m8n8.x4.shared.b16 {%0,%1,%2,%3}, [%4];"
                 : "=r"(r[0]), "=r"(r[1]), "=r"(r[2]), "=r"(r[3]) : "r"(addr));
}
__device__ __forceinline__ void mma16816(float* c, const uint32_t* a, const uint32_t* b) {
    asm volatile(
        "mma.sync.aligned.m16n8k16.row.col.f32.f16.f16.f32 "
        "{%0,%1,%2,%3}, {%4,%5,%6,%7}, {%8,%9}, {%0,%1,%2,%3};"
        : "+f"(c[0]), "+f"(c[1]), "+f"(c[2]), "+f"(c[3])
        : "r"(a[0]), "r"(a[1]), "r"(a[2]), "r"(a[3]), "r"(b[0]), "r"(b[1]));
}
__device__ __forceinline__ unsigned pack_f16(float lo, float hi) {
    __half2 p = __halves2half2(__float2half_rn(lo), __float2half_rn(hi));
    return *reinterpret_cast<unsigned*>(&p);
}
__device__ __forceinline__ float eluf(float v) { return v > 0.f ? v : expm1f(v); }
// swizzled byte offset for (row, 16B k-group) within a [rows]x128 fp16 tile
__device__ __forceinline__ uint32_t swz(int row, int kg) {
    return ((uint32_t)row << 8) + (((uint32_t)(kg ^ (row & 7))) << 4);
}

// ---------------- small kernels ----------------
__global__ void zero_kernel() {
    int g = blockIdx.x * 256 + threadIdx.x;
    if (g < NN_MAX) g_hist[g] = 0;
    if (g < C) { g_s1[g] = 0.f; g_q1[g] = 0.f; g_s2[g] = 0.f; g_q2[g] = 0.f; }
}

// split w1/w2 into hi/lo fp16 blobs, swizzled [n][k]
__global__ void prep_w(const float* __restrict__ w1, const float* __restrict__ w2) {
    int t = blockIdx.x * 256 + threadIdx.x;   // 0..2047
    if (t >= 2048) return;
    int n = t >> 4;              // output channel 0..127
    int kg = t & 15;             // k group of 8
    uint32_t sw = swz(n, kg);
#pragma unroll
    for (int m = 0; m < 4; m++) {
        const float* src = (m < 2 ? w1 : w2) + (size_t)n * 256 + (m & 1) * 128 + kg * 8;
        float hf[8], lf[8];
#pragma unroll
        for (int j = 0; j < 8; j++) {
            float v = src[j];
            __half h = __float2half_rn(v);
            hf[j] = __half2float(h);
            lf[j] = v - hf[j];
        }
        uint4 uh, ul;
        uh.x = pack_f16(hf[0], hf[1]); uh.y = pack_f16(hf[2], hf[3]);
        uh.z = pack_f16(hf[4], hf[5]); uh.w = pack_f16(hf[6], hf[7]);
        ul.x = pack_f16(lf[0], lf[1]); ul.y = pack_f16(lf[2], lf[3]);
        ul.z = pack_f16(lf[4], lf[5]); ul.w = pack_f16(lf[6], lf[7]);
        *(uint4*)((char*)g_wblob[m * 2 + 0] + sw) = uh;
        *(uint4*)((char*)g_wblob[m * 2 + 1] + sw) = ul;
    }
}

// ---------------- counting sort of edges by destination ----------------
__global__ void hist_kernel(const int* __restrict__ col, int E) {
    int e = blockIdx.x * 256 + threadIdx.x;
    if (e < E) atomicAdd(&g_hist[col[e]], 1);
}

__global__ void scan1_kernel(int n) {
    __shared__ int wsum[8];
    int i = blockIdx.x * 256 + threadIdx.x;
    int lane = threadIdx.x & 31, w = threadIdx.x >> 5;
    int v = (i < n) ? g_hist[i] : 0;
    int x = v;
#pragma unroll
    for (int o = 1; o < 32; o <<= 1) {
        int y = __shfl_up_sync(~0u, x, o); if (lane >= o) x += y;
    }
    if (lane == 31) wsum[w] = x;
    __syncthreads();
    if (w == 0) {
        int s = (lane < 8) ? wsum[lane] : 0;
#pragma unroll
        for (int o = 1; o < 8; o <<= 1) {
            int y = __shfl_up_sync(~0u, s, o); if (lane >= o) s += y;
        }
        if (lane < 8) wsum[lane] = s;
    }
    __syncthreads();
    int base = (w > 0) ? wsum[w - 1] : 0;
    int incl = x + base;
    if (i < n) g_off[i] = incl - v;
    if (threadIdx.x == 255) g_bsum[blockIdx.x] = incl;
}

__global__ void scan2_kernel(int nb) {
    __shared__ int wsum[8];
    int t = threadIdx.x, lane = t & 31, w = t >> 5;
    int v = (t < nb) ? g_bsum[t] : 0;
    int x = v;
#pragma unroll
    for (int o = 1; o < 32; o <<= 1) {
        int y = __shfl_up_sync(~0u, x, o); if (lane >= o) x += y;
    }
    if (lane == 31) wsum[w] = x;
    __syncthreads();
    if (w == 0) {
        int s = (lane < 8) ? wsum[lane] : 0;
#pragma unroll
        for (int o = 1; o < 8; o <<= 1) {
            int y = __shfl_up_sync(~0u, s, o); if (lane >= o) s += y;
        }
        if (lane < 8) wsum[lane] = s;
    }
    __syncthreads();
    int base = (w > 0) ? wsum[w - 1] : 0;
    if (t < nb) g_bsum[t] = x + base - v;   // exclusive block offsets
}

__global__ void scan3_kernel(int n) {
    int i = blockIdx.x * 256 + threadIdx.x;
    if (i < n) {
        int o = g_off[i] + g_bsum[blockIdx.x];
        g_off[i] = o;
        g_cur[i] = o;
    }
}

__global__ void permute_kernel(const int* __restrict__ col, int E) {
    int e = blockIdx.x * 256 + threadIdx.x;
    if (e < E) {
        int p = atomicAdd(&g_cur[col[e]], 1);
        g_perm[p] = e;
    }
}

// ---------------- persistent mma.sync GEMM (BM=128, 32x64 warp tiles) ----------------
// MODE 0: g_xa  = x @ w1a^T                               (fp32 out)
// MODE 1: g_h(fp16) = ea @ w1b^T + g_xa[row[m]] + b1      (+ fused BN1 stats)
// MODE 2: g_pre = x @ w2a^T + (agg/cnt) @ w2b^T + b2      (+ fused BN2 stats; K=256)
// smem: BH 0 (32K) / AH 32K (32K) / AL 64K (32K) -> 96 KB, 2 CTAs/SM
// fp16 split on A only: (ah+al)*bh = a*bh ; error = a*(b-bh) ~ 2^-11 rel
template <int MODE>
__global__ void __launch_bounds__(256, 2) mm_kernel(
    const float* __restrict__ A, const float* __restrict__ bias,
    const int* __restrict__ rowidx, int M)
{
    extern __shared__ __align__(16) char sm[];
    constexpr int BH = 0, AH = 32768, AL = 65536;
    constexpr int KT = (MODE == 2) ? 2 : 1;
    constexpr bool STATS = (MODE == 1) || (MODE == 2);

    const int tid = threadIdx.x;
    const int lane = tid & 31, wid = tid >> 5;
    const int wm = wid >> 1;          // 0..3 : 32-row group
    const int wn = wid & 1;           // 0..1 : 64-col group

    float* Sg = (MODE == 1) ? g_s1 : g_s2;
    float* Qg = (MODE == 1) ? g_q1 : g_q2;

    // ---- stage B once for single-k-tile modes ----
    if (KT == 1) {
        const uint4* bh = (const uint4*)g_wblob[(MODE == 0) ? 0 : 2];
        for (int i = tid; i < 2048; i += 256)
            ((uint4*)(sm + BH))[i] = bh[i];
    }

    const uint32_t sb = smem_u32(sm);
    const uint32_t rx = lane & 7;
    const uint32_t rbA = (uint32_t)(wm * 32 + (lane & 15)) << 8;
    const uint32_t kgoA = lane >> 4;
    uint32_t rbB[4];
#pragma unroll
    for (int nf2 = 0; nf2 < 4; nf2++)
        rbB[nf2] = (uint32_t)(wn * 64 + nf2 * 16 + ((lane >> 4) << 3) + (lane & 7)) << 8;
    const uint32_t kgoB = (lane >> 3) & 1;

    const int np = (lane & 3) * 2;
    // register BN stats accumulated across tiles
    float s0[8], s1[8], q0[8], q1[8];
#pragma unroll
    for (int nf = 0; nf < 8; nf++) { s0[nf] = s1[nf] = q0[nf] = q1[nf] = 0.f; }

    const int tiles = (M + 127) >> 7;
    for (int t = blockIdx.x; t < tiles; t += gridDim.x) {
        const int mbase = t * 128;

        float acc[2][8][4];
#pragma unroll
        for (int mi = 0; mi < 2; mi++)
#pragma unroll
            for (int nf = 0; nf < 8; nf++)
#pragma unroll
                for (int cc = 0; cc < 4; cc++) acc[mi][nf][cc] = 0.f;

#pragma unroll
        for (int kt = 0; kt < KT; kt++) {
            __syncthreads();   // prior mainloop done before overwriting smem
            if (KT == 2) {     // fused node GEMM: re-stage B per k-tile
                const uint4* bh = (const uint4*)g_wblob[4 + kt * 2];
                for (int i = tid; i < 2048; i += 256)
                    ((uint4*)(sm + BH))[i] = bh[i];
            }
            // ---- stage + split A tile (128 x 128) to fp16 hi/lo ----
            const float* Ap = (MODE == 2 && kt == 1) ? (const float*)g_agg : A;
#pragma unroll
            for (int it = 0; it < 8; it++) {
                int gi = it * 256 + tid;        // 0..2047
                int r = gi >> 4, kg = gi & 15;
                int m = mbase + r; if (m >= M) m = M - 1;
                const float* src = Ap + (size_t)m * C + kg * 8;
                float4 va, vb;
                if (MODE == 1) {               // streaming: keep xa resident in L2
                    va = __ldcs((const float4*)src);
                    vb = __ldcs((const float4*)src + 1);
                } else {
                    va = *(const float4*)src;
                    vb = *(const float4*)(src + 4);
                }
                float v[8] = {va.x, va.y, va.z, va.w, vb.x, vb.y, vb.z, vb.w};
                if (MODE == 2 && kt == 1) {
                    float s = __frcp_rn(fmaxf((float)g_hist[m], 1.f));
#pragma unroll
                    for (int j = 0; j < 8; j++) v[j] *= s;
                }
                float hf[8], lf[8];
#pragma unroll
                for (int j = 0; j < 8; j++) {
                    __half h = __float2half_rn(v[j]);
                    hf[j] = __half2float(h);
                    lf[j] = v[j] - hf[j];
                }
                uint4 uh, ul;
                uh.x = pack_f16(hf[0], hf[1]); uh.y = pack_f16(hf[2], hf[3]);
                uh.z = pack_f16(hf[4], hf[5]); uh.w = pack_f16(hf[6], hf[7]);
                ul.x = pack_f16(lf[0], lf[1]); ul.y = pack_f16(lf[2], lf[3]);
                ul.z = pack_f16(lf[4], lf[5]); ul.w = pack_f16(lf[6], lf[7]);
                uint32_t sw = swz(r, kg);
                *(uint4*)(sm + AH + sw) = uh;
                *(uint4*)(sm + AL + sw) = ul;
            }
            __syncthreads();

            // ---- MMA mainloop: 8 k16 steps ----
#pragma unroll
            for (int ks = 0; ks < 8; ks++) {
                uint32_t offA = ((2 * ks + kgoA) ^ rx) << 4;
                uint32_t offB = ((2 * ks + kgoB) ^ rx) << 4;
                uint32_t ah[2][4], al[2][4];
                ldsm4(ah[0], sb + AH + rbA + offA);
                ldsm4(ah[1], sb + AH + rbA + (16 << 8) + offA);
                ldsm4(al[0], sb + AL + rbA + offA);
                ldsm4(al[1], sb + AL + rbA + (16 << 8) + offA);
#pragma unroll
                for (int nf2 = 0; nf2 < 4; nf2++) {
                    uint32_t bh[4];
                    ldsm4(bh, sb + BH + rbB[nf2] + offB);
#pragma unroll
                    for (int j = 0; j < 2; j++) {
                        const uint32_t* fh = &bh[j * 2];
#pragma unroll
                        for (int mi = 0; mi < 2; mi++) {
                            mma16816(acc[mi][nf2 * 2 + j], ah[mi], fh);
                            mma16816(acc[mi][nf2 * 2 + j], al[mi], fh);
                        }
                    }
                }
            }
        }

        // ---- epilogue ----
        const int g = lane >> 2;
#pragma unroll
        for (int mi = 0; mi < 2; mi++) {
#pragma unroll
            for (int h = 0; h < 2; h++) {
                int r = wm * 32 + mi * 16 + h * 8 + g;
                int m = mbase + r;
                bool valid = (m < M);
                const float* xr = nullptr;
                if (MODE == 1 && valid) xr = g_xa + (size_t)rowidx[m] * C;
#pragma unroll
                for (int nf = 0; nf < 8; nf++) {
                    int col = wn * 64 + nf * 8 + np;
                    float o0 = acc[mi][nf][h * 2 + 0];
                    float o1 = acc[mi][nf][h * 2 + 1];
                    if (MODE != 0 && valid) {
                        o0 += bias[col]; o1 += bias[col + 1];
                    }
                    if (MODE == 1 && valid) {
                        float2 xv = *(const float2*)(xr + col);
                        o0 += xv.x; o1 += xv.y;
                    }
                    if (valid) {
                        if (MODE == 0) {
                            *(float2*)(g_xa + (size_t)m * C + col) = make_float2(o0, o1);
                        } else if (MODE == 1) {
                            __half* orow = (__half*)g_h + (size_t)m * C;
                            *(__half2*)(orow + col) = __floats2half2_rn(o0, o1);
                        } else {
                            *(float2*)(g_pre + (size_t)m * C + col) = make_float2(o0, o1);
                        }
                        if (STATS) {
                            s0[nf] += o0; q0[nf] += o0 * o0;
                            s1[nf] += o1; q1[nf] += o1 * o1;
                        }
                    }
                }
            }
        }
    }

    // ---- flush BN stats once per warp ----
    if (STATS) {
#pragma unroll
        for (int nf = 0; nf < 8; nf++) {
#pragma unroll
            for (int off = 4; off <= 16; off <<= 1) {
                s0[nf] += __shfl_xor_sync(0xffffffffu, s0[nf], off);
                s1[nf] += __shfl_xor_sync(0xffffffffu, s1[nf], off);
                q0[nf] += __shfl_xor_sync(0xffffffffu, q0[nf], off);
                q1[nf] += __shfl_xor_sync(0xffffffffu, q1[nf], off);
            }
        }
        if (lane < 4) {
#pragma unroll
            for (int nf = 0; nf < 8; nf++) {
                int col = wn * 64 + nf * 8 + lane * 2;
                atomicAdd(&Sg[col], s0[nf]); atomicAdd(&Sg[col + 1], s1[nf]);
                atomicAdd(&Qg[col], q0[nf]); atomicAdd(&Qg[col + 1], q1[nf]);
            }
        }
    }
}

// ---------------- BN coefficient finalize ----------------
__global__ void finalize_kernel(int sel, const float* __restrict__ bnw,
                                const float* __restrict__ bnb, float minv) {
    int j = threadIdx.x;
    float s  = sel ? g_s2[j] : g_s1[j];
    float q  = sel ? g_q2[j] : g_q1[j];
    float mu = s * minv;
    float var = q * minv - mu * mu;
    float r = rsqrtf(var + BN_EPS);
    float a = r * bnw[j];
    float c = bnb[j] - mu * a;
    if (sel) { g_a2[j] = a; g_c2[j] = c; }
    else     { g_a1[j] = a; g_c1[j] = c; }
}

// ---------------- BN1 + ELU + CSR segment-sum over fp16 h (warp/node) ----------------
__global__ void __launch_bounds__(256) segsum_kernel(int n) {
    int wg = (blockIdx.x * 256 + threadIdx.x) >> 5;
    int lane = threadIdx.x & 31;
    if (wg >= n) return;
    int s = g_off[wg];
    int cnt = g_hist[wg];
    int cq = lane * 4;
    float4 a = *(const float4*)(g_a1 + cq);
    float4 c = *(const float4*)(g_c1 + cq);
    const __half* hp = (const __half*)g_h;
    float4 acc = {0.f, 0.f, 0.f, 0.f};
    auto accum = [&](uint2 raw) {
        float2 f0 = __half22float2(*(__half2*)&raw.x);
        float2 f1 = __half22float2(*(__half2*)&raw.y);
        acc.x += eluf(fmaf(f0.x, a.x, c.x));
        acc.y += eluf(fmaf(f0.y, a.y, c.y));
        acc.z += eluf(fmaf(f1.x, a.z, c.z));
        acc.w += eluf(fmaf(f1.y, a.w, c.w));
    };
    int j = 0;
    for (; j + 4 <= cnt; j += 4) {
        int e0 = __ldg(&g_perm[s + j + 0]);
        int e1 = __ldg(&g_perm[s + j + 1]);
        int e2 = __ldg(&g_perm[s + j + 2]);
        int e3 = __ldg(&g_perm[s + j + 3]);
        uint2 r0 = __ldcs((const uint2*)(hp + (size_t)e0 * C) + lane);
        uint2 r1 = __ldcs((const uint2*)(hp + (size_t)e1 * C) + lane);
        uint2 r2 = __ldcs((const uint2*)(hp + (size_t)e2 * C) + lane);
        uint2 r3 = __ldcs((const uint2*)(hp + (size_t)e3 * C) + lane);
        accum(r0); accum(r1); accum(r2); accum(r3);
    }
    for (; j < cnt; j++) {
        int e = __ldg(&g_perm[s + j]);
        uint2 r = __ldcs((const uint2*)(hp + (size_t)e * C) + lane);
        accum(r);
    }
    *(float4*)(g_agg + (size_t)wg * C + cq) = acc;
}

// ---------------- BN2 + ELU -> output ----------------
__global__ void final_kernel(float* __restrict__ out, int n) {
    int g = blockIdx.x * 256 + threadIdx.x;
    if (g >= n * 32) return;
    int cq = (g & 31) * 4;
    float4 v = *(const float4*)(g_pre + (size_t)g * 4);
    float4 a = *(const float4*)(g_a2 + cq);
    float4 c = *(const float4*)(g_c2 + cq);
    float4 o;
    o.x = eluf(fmaf(v.x, a.x, c.x));
    o.y = eluf(fmaf(v.y, a.y, c.y));
    o.z = eluf(fmaf(v.z, a.z, c.z));
    o.w = eluf(fmaf(v.w, a.w, c.w));
    *(float4*)(out + (size_t)g * 4) = o;
}

// ---------------- launch ----------------
extern "C" void kernel_launch(void* const* d_in, const int* in_sizes, int n_in,
                              void* d_out, int out_size) {
    const float* x    = (const float*)d_in[0];
    const int*   ei   = (const int*)d_in[1];
    const float* ea   = (const float*)d_in[2];
    const float* w1   = (const float*)d_in[5];
    const float* b1   = (const float*)d_in[6];
    const float* bn1w = (const float*)d_in[7];
    const float* bn1b = (const float*)d_in[8];
    const float* w2   = (const float*)d_in[9];
    const float* b2   = (const float*)d_in[10];
    const float* bn2w = (const float*)d_in[11];
    const float* bn2b = (const float*)d_in[12];
    float* out = (float*)d_out;

    int n = in_sizes[0] / C;           // 50000
    int E = in_sizes[2] / C;           // 800000
    const int* row = ei;
    const int* col = ei + E;

    const int SMEM = 98304;            // 96 KB -> 2 CTAs/SM
    cudaFuncSetAttribute(mm_kernel<0>, cudaFuncAttributeMaxDynamicSharedMemorySize, SMEM);
    cudaFuncSetAttribute(mm_kernel<1>, cudaFuncAttributeMaxDynamicSharedMemorySize, SMEM);
    cudaFuncSetAttribute(mm_kernel<2>, cudaFuncAttributeMaxDynamicSharedMemorySize, SMEM);

    int nb = (n + 255) / 256;          // scan blocks (<=256 required)

    const int GRID = 296;              // 2 persistent CTAs per SM
    int ngrid = min(GRID, (n + 127) / 128);
    int egrid = min(GRID, (E + 127) / 128);

    // launch order chosen so mm_kernel<1> is launch #4 (the profiled slot)
    zero_kernel<<<(NN_MAX + 255) / 256, 256>>>();                 // 1
    prep_w<<<8, 256>>>(w1, w2);                                   // 2
    mm_kernel<0><<<ngrid, 256, SMEM>>>(x, nullptr, nullptr, n);   // 3: xa = x @ w1a^T
    mm_kernel<1><<<egrid, 256, SMEM>>>(ea, b1, row, E);           // 4: h = ea@w1b^T + xa[row] + b1

    // counting sort of edges by destination node (independent of GEMMs)
    hist_kernel<<<(E + 255) / 256, 256>>>(col, E);
    scan1_kernel<<<nb, 256>>>(n);
    scan2_kernel<<<1, 256>>>(nb);
    scan3_kernel<<<nb, 256>>>(n);
    permute_kernel<<<(E + 255) / 256, 256>>>(col, E);

    finalize_kernel<<<1, C>>>(0, bn1w, bn1b, 1.f / (float)E);

    // agg = segment_sum(elu(bn1(h)))  (CSR over fp16 h, no float atomics)
    segsum_kernel<<<(n * 32 + 255) / 256, 256>>>(n);

    // pre = x @ w2a^T + (agg/cnt) @ w2b^T + b2   (fused K=256, stats fused)
    mm_kernel<2><<<ngrid, 256, SMEM>>>(x, b2, nullptr, n);
    finalize_kernel<<<1, C>>>(1, bn2w, bn2b, 1.f / (float)n);

    final_kernel<<<(n * 32 + 255) / 256, 256>>>(out, n);
}

// round 15
// speedup vs baseline: 1.4346x; 1.1040x over previous
#include <cuda_runtime.h>
#include <cuda_fp16.h>
#include <math.h>
#include <stdint.h>

#define C 128
#define NE_MAX 800000
#define NN_MAX 50000
#define BN_EPS 1e-5f

// ---------------- scratch (device globals; no runtime alloc) ----------------
__device__ float g_h[(size_t)NE_MAX * C / 2]; // edge MLP pre-BN output (fp16 packed)
__device__ float g_xa[(size_t)NN_MAX * C];    // x @ w1a^T
__device__ float g_agg[(size_t)NN_MAX * C];   // per-node mean numerator
__device__ float g_pre[(size_t)NN_MAX * C];   // node MLP pre-BN output
__device__ int   g_hist[NN_MAX];              // edge count per node
__device__ int   g_off[NN_MAX];               // CSR start offsets
__device__ int   g_cur[NN_MAX];               // permute cursors
__device__ int   g_bsum[256];                 // scan block sums
__device__ int   g_perm[NE_MAX];              // edges sorted by col
__device__ float g_s1[C], g_q1[C], g_s2[C], g_q2[C];
__device__ float g_a1[C], g_c1[C], g_a2[C], g_c2[C];
// fp16 weight blobs in smem-swizzled [n][k] layout:
// 0 = w1a ; 1 = w1b ; 2 = w2a ; 3 = w2b   (single-term fp16)
__device__ __align__(16) uint16_t g_wblob[4][128 * 128];

// ---------------- helpers ----------------
__device__ __forceinline__ uint32_t smem_u32(const void* p) {
    return (uint32_t)__cvta_generic_to_shared(p);
}
__device__ __forceinline__ void ldsm4(uint32_t* r, uint32_t addr) {
    asm volatile("ldmatrix.sync.aligned.m8n8.x4.shared.b16 {%0,%1,%2,%3}, [%4];"
                 : "=r"(r[0]), "=r"(r[1]), "=r"(r[2]), "=r"(r[3]) : "r"(addr));
}
__device__ __forceinline__ void mma16816(float* c, const uint32_t* a, const uint32_t* b) {
    asm volatile(
        "mma.sync.aligned.m16n8k16.row.col.f32.f16.f16.f32 "
        "{%0,%1,%2,%3}, {%4,%5,%6,%7}, {%8,%9}, {%0,%1,%2,%3};"
        : "+f"(c[0]), "+f"(c[1]), "+f"(c[2]), "+f"(c[3])
        : "r"(a[0]), "r"(a[1]), "r"(a[2]), "r"(a[3]), "r"(b[0]), "r"(b[1]));
}
__device__ __forceinline__ unsigned pack2(float a, float b) {
    __half2 p = __floats2half2_rn(a, b);
    return *reinterpret_cast<unsigned*>(&p);
}
__device__ __forceinline__ float eluf(float v) { return v > 0.f ? v : expm1f(v); }
// swizzled byte offset for (row, 16B k-group) within a [rows]x128 fp16 tile
__device__ __forceinline__ uint32_t swz(int row, int kg) {
    return ((uint32_t)row << 8) + (((uint32_t)(kg ^ (row & 7))) << 4);
}

// ---------------- small kernels ----------------
__global__ void zero_kernel() {
    int g = blockIdx.x * 256 + threadIdx.x;
    if (g < NN_MAX) g_hist[g] = 0;
    if (g < C) { g_s1[g] = 0.f; g_q1[g] = 0.f; g_s2[g] = 0.f; g_q2[g] = 0.f; }
}

// convert w1/w2 to fp16 blobs, swizzled [n][k]
__global__ void prep_w(const float* __restrict__ w1, const float* __restrict__ w2) {
    int t = blockIdx.x * 256 + threadIdx.x;   // 0..2047
    if (t >= 2048) return;
    int n = t >> 4;              // output channel 0..127
    int kg = t & 15;             // k group of 8
    uint32_t sw = swz(n, kg);
#pragma unroll
    for (int m = 0; m < 4; m++) {
        const float* src = (m < 2 ? w1 : w2) + (size_t)n * 256 + (m & 1) * 128 + kg * 8;
        uint4 u;
        u.x = pack2(src[0], src[1]);
        u.y = pack2(src[2], src[3]);
        u.z = pack2(src[4], src[5]);
        u.w = pack2(src[6], src[7]);
        *(uint4*)((char*)g_wblob[m] + sw) = u;
    }
}

// ---------------- counting sort of edges by destination ----------------
__global__ void hist_kernel(const int* __restrict__ col, int E) {
    int e = blockIdx.x * 256 + threadIdx.x;
    if (e < E) atomicAdd(&g_hist[col[e]], 1);
}

__global__ void scan1_kernel(int n) {
    __shared__ int wsum[8];
    int i = blockIdx.x * 256 + threadIdx.x;
    int lane = threadIdx.x & 31, w = threadIdx.x >> 5;
    int v = (i < n) ? g_hist[i] : 0;
    int x = v;
#pragma unroll
    for (int o = 1; o < 32; o <<= 1) {
        int y = __shfl_up_sync(~0u, x, o); if (lane >= o) x += y;
    }
    if (lane == 31) wsum[w] = x;
    __syncthreads();
    if (w == 0) {
        int s = (lane < 8) ? wsum[lane] : 0;
#pragma unroll
        for (int o = 1; o < 8; o <<= 1) {
            int y = __shfl_up_sync(~0u, s, o); if (lane >= o) s += y;
        }
        if (lane < 8) wsum[lane] = s;
    }
    __syncthreads();
    int base = (w > 0) ? wsum[w - 1] : 0;
    int incl = x + base;
    if (i < n) g_off[i] = incl - v;
    if (threadIdx.x == 255) g_bsum[blockIdx.x] = incl;
}

__global__ void scan2_kernel(int nb) {
    __shared__ int wsum[8];
    int t = threadIdx.x, lane = t & 31, w = t >> 5;
    int v = (t < nb) ? g_bsum[t] : 0;
    int x = v;
#pragma unroll
    for (int o = 1; o < 32; o <<= 1) {
        int y = __shfl_up_sync(~0u, x, o); if (lane >= o) x += y;
    }
    if (lane == 31) wsum[w] = x;
    __syncthreads();
    if (w == 0) {
        int s = (lane < 8) ? wsum[lane] : 0;
#pragma unroll
        for (int o = 1; o < 8; o <<= 1) {
            int y = __shfl_up_sync(~0u, s, o); if (lane >= o) s += y;
        }
        if (lane < 8) wsum[lane] = s;
    }
    __syncthreads();
    int base = (w > 0) ? wsum[w - 1] : 0;
    if (t < nb) g_bsum[t] = x + base - v;   // exclusive block offsets
}

__global__ void scan3_kernel(int n) {
    int i = blockIdx.x * 256 + threadIdx.x;
    if (i < n) {
        int o = g_off[i] + g_bsum[blockIdx.x];
        g_off[i] = o;
        g_cur[i] = o;
    }
}

__global__ void permute_kernel(const int* __restrict__ col, int E) {
    int e = blockIdx.x * 256 + threadIdx.x;
    if (e < E) {
        int p = atomicAdd(&g_cur[col[e]], 1);
        g_perm[p] = e;
    }
}

// ---------------- persistent mma.sync GEMM (BM=128, single fp16, dbl-buffered A) ----------------
// MODE 0: g_xa  = x @ w1a^T                               (fp32 out)
// MODE 1: g_h(fp16) = ea @ w1b^T + g_xa[row[m]] + b1      (+ fused BN1 stats)
// MODE 2: g_pre = x @ w2a^T + (agg/cnt) @ w2b^T + b2      (+ fused BN2 stats; K=256)
// smem: BH 0 (32K) / A0 32K (32K) / A1 64K (32K) -> 96 KB, 2 CTAs/SM
// One __syncthreads per tile (stage into alternate buffer overlaps stragglers).
template <int MODE>
__global__ void __launch_bounds__(256, 2) mm_kernel(
    const float* __restrict__ A, const float* __restrict__ bias,
    const int* __restrict__ rowidx, int M)
{
    extern __shared__ __align__(16) char sm[];
    constexpr int BH = 0, A0 = 32768;
    constexpr int KT = (MODE == 2) ? 2 : 1;
    constexpr bool STATS = (MODE == 1) || (MODE == 2);

    const int tid = threadIdx.x;
    const int lane = tid & 31, wid = tid >> 5;
    const int wm = wid >> 1;          // 0..3 : 32-row group
    const int wn = wid & 1;           // 0..1 : 64-col group

    float* Sg = (MODE == 1) ? g_s1 : g_s2;
    float* Qg = (MODE == 1) ? g_q1 : g_q2;

    // ---- stage B once for single-k-tile modes ----
    if (KT == 1) {
        const uint4* bh = (const uint4*)g_wblob[(MODE == 0) ? 0 : 1];
        for (int i = tid; i < 2048; i += 256)
            ((uint4*)(sm + BH))[i] = bh[i];
    }

    const uint32_t sb = smem_u32(sm);
    const uint32_t rx = lane & 7;
    const uint32_t rbA = (uint32_t)(wm * 32 + (lane & 15)) << 8;
    const uint32_t kgoA = lane >> 4;
    uint32_t rbB[4];
#pragma unroll
    for (int nf2 = 0; nf2 < 4; nf2++)
        rbB[nf2] = (uint32_t)(wn * 64 + nf2 * 16 + ((lane >> 4) << 3) + (lane & 7)) << 8;
    const uint32_t kgoB = (lane >> 3) & 1;

    const int np = (lane & 3) * 2;
    float s0[8], s1[8], q0[8], q1[8];
#pragma unroll
    for (int nf = 0; nf < 8; nf++) { s0[nf] = s1[nf] = q0[nf] = q1[nf] = 0.f; }

    // ---- single-term fp16 A staging into buffer `abase` ----
    auto stA = [&](const float* Ap, int mbase, uint32_t abase, bool scale) {
#pragma unroll
        for (int it = 0; it < 8; it++) {
            int gi = it * 256 + tid;        // 0..2047
            int r = gi >> 4, kg = gi & 15;
            int m = mbase + r; if (m >= M) m = M - 1;
            const float* src = Ap + (size_t)m * C + kg * 8;
            float4 va, vb;
            if (MODE == 1) {
                va = __ldcs((const float4*)src);
                vb = __ldcs((const float4*)src + 1);
            } else {
                va = *(const float4*)src;
                vb = *(const float4*)(src + 4);
            }
            if (scale) {
                float s = __frcp_rn(fmaxf((float)g_hist[m], 1.f));
                va.x *= s; va.y *= s; va.z *= s; va.w *= s;
                vb.x *= s; vb.y *= s; vb.z *= s; vb.w *= s;
            }
            uint4 u;
            u.x = pack2(va.x, va.y); u.y = pack2(va.z, va.w);
            u.z = pack2(vb.x, vb.y); u.w = pack2(vb.z, vb.w);
            *(uint4*)(sm + abase + swz(r, kg)) = u;
        }
    };

    const int tiles = (M + 127) >> 7;
    int buf = 0;
    for (int t = blockIdx.x; t < tiles; t += gridDim.x) {
        const int mbase = t * 128;

        float acc[2][8][4];
#pragma unroll
        for (int mi = 0; mi < 2; mi++)
#pragma unroll
            for (int nf = 0; nf < 8; nf++)
#pragma unroll
                for (int cc = 0; cc < 4; cc++) acc[mi][nf][cc] = 0.f;

#pragma unroll
        for (int kt = 0; kt < KT; kt++) {
            if (KT == 2) {     // fused node GEMM: re-stage B per k-tile
                __syncthreads();
                const uint4* bh = (const uint4*)g_wblob[2 + kt];
                for (int i = tid; i < 2048; i += 256)
                    ((uint4*)(sm + BH))[i] = bh[i];
            }
            const float* Ap = (MODE == 2 && kt == 1) ? (const float*)g_agg : A;
            const uint32_t abase = A0 + buf * 32768;
            stA(Ap, mbase, abase, MODE == 2 && kt == 1);
            __syncthreads();

            // ---- MMA mainloop: 8 k16 steps ----
#pragma unroll
            for (int ks = 0; ks < 8; ks++) {
                uint32_t offA = ((2 * ks + kgoA) ^ rx) << 4;
                uint32_t offB = ((2 * ks + kgoB) ^ rx) << 4;
                uint32_t ah[2][4];
                ldsm4(ah[0], sb + abase + rbA + offA);
                ldsm4(ah[1], sb + abase + rbA + (16 << 8) + offA);
#pragma unroll
                for (int nf2 = 0; nf2 < 4; nf2++) {
                    uint32_t bh[4];
                    ldsm4(bh, sb + BH + rbB[nf2] + offB);
#pragma unroll
                    for (int j = 0; j < 2; j++) {
                        const uint32_t* fh = &bh[j * 2];
                        mma16816(acc[0][nf2 * 2 + j], ah[0], fh);
                        mma16816(acc[1][nf2 * 2 + j], ah[1], fh);
                    }
                }
            }
            buf ^= 1;
        }

        // ---- epilogue ----
        const int g = lane >> 2;
#pragma unroll
        for (int mi = 0; mi < 2; mi++) {
#pragma unroll
            for (int h = 0; h < 2; h++) {
                int r = wm * 32 + mi * 16 + h * 8 + g;
                int m = mbase + r;
                bool valid = (m < M);
                const float* xr = nullptr;
                if (MODE == 1 && valid) xr = g_xa + (size_t)rowidx[m] * C;
#pragma unroll
                for (int nf = 0; nf < 8; nf++) {
                    int col = wn * 64 + nf * 8 + np;
                    float o0 = acc[mi][nf][h * 2 + 0];
                    float o1 = acc[mi][nf][h * 2 + 1];
                    if (MODE != 0 && valid) {
                        o0 += bias[col]; o1 += bias[col + 1];
                    }
                    if (MODE == 1 && valid) {
                        float2 xv = *(const float2*)(xr + col);
                        o0 += xv.x; o1 += xv.y;
                    }
                    if (valid) {
                        if (MODE == 0) {
                            *(float2*)(g_xa + (size_t)m * C + col) = make_float2(o0, o1);
                        } else if (MODE == 1) {
                            __half* orow = (__half*)g_h + (size_t)m * C;
                            *(__half2*)(orow + col) = __floats2half2_rn(o0, o1);
                        } else {
                            *(float2*)(g_pre + (size_t)m * C + col) = make_float2(o0, o1);
                        }
                        if (STATS) {
                            s0[nf] += o0; q0[nf] += o0 * o0;
                            s1[nf] += o1; q1[nf] += o1 * o1;
                        }
                    }
                }
            }
        }
    }

    // ---- flush BN stats once per warp ----
    if (STATS) {
#pragma unroll
        for (int nf = 0; nf < 8; nf++) {
#pragma unroll
            for (int off = 4; off <= 16; off <<= 1) {
                s0[nf] += __shfl_xor_sync(0xffffffffu, s0[nf], off);
                s1[nf] += __shfl_xor_sync(0xffffffffu, s1[nf], off);
                q0[nf] += __shfl_xor_sync(0xffffffffu, q0[nf], off);
                q1[nf] += __shfl_xor_sync(0xffffffffu, q1[nf], off);
            }
        }
        if (lane < 4) {
#pragma unroll
            for (int nf = 0; nf < 8; nf++) {
                int col = wn * 64 + nf * 8 + lane * 2;
                atomicAdd(&Sg[col], s0[nf]); atomicAdd(&Sg[col + 1], s1[nf]);
                atomicAdd(&Qg[col], q0[nf]); atomicAdd(&Qg[col + 1], q1[nf]);
            }
        }
    }
}

// ---------------- BN coefficient finalize ----------------
__global__ void finalize_kernel(int sel, const float* __restrict__ bnw,
                                const float* __restrict__ bnb, float minv) {
    int j = threadIdx.x;
    float s  = sel ? g_s2[j] : g_s1[j];
    float q  = sel ? g_q2[j] : g_q1[j];
    float mu = s * minv;
    float var = q * minv - mu * mu;
    float r = rsqrtf(var + BN_EPS);
    float a = r * bnw[j];
    float c = bnb[j] - mu * a;
    if (sel) { g_a2[j] = a; g_c2[j] = c; }
    else     { g_a1[j] = a; g_c1[j] = c; }
}

// ---------------- BN1 + ELU + CSR segment-sum over fp16 h (warp/node) ----------------
__global__ void __launch_bounds__(256) segsum_kernel(int n) {
    int wg = (blockIdx.x * 256 + threadIdx.x) >> 5;
    int lane = threadIdx.x & 31;
    if (wg >= n) return;
    int s = g_off[wg];
    int cnt = g_hist[wg];
    int cq = lane * 4;
    float4 a = *(const float4*)(g_a1 + cq);
    float4 c = *(const float4*)(g_c1 + cq);
    const __half* hp = (const __half*)g_h;
    float4 acc = {0.f, 0.f, 0.f, 0.f};
    auto accum = [&](uint2 raw) {
        float2 f0 = __half22float2(*(__half2*)&raw.x);
        float2 f1 = __half22float2(*(__half2*)&raw.y);
        acc.x += eluf(fmaf(f0.x, a.x, c.x));
        acc.y += eluf(fmaf(f0.y, a.y, c.y));
        acc.z += eluf(fmaf(f1.x, a.z, c.z));
        acc.w += eluf(fmaf(f1.y, a.w, c.w));
    };
    int j = 0;
    for (; j + 4 <= cnt; j += 4) {
        int e0 = __ldg(&g_perm[s + j + 0]);
        int e1 = __ldg(&g_perm[s + j + 1]);
        int e2 = __ldg(&g_perm[s + j + 2]);
        int e3 = __ldg(&g_perm[s + j + 3]);
        uint2 r0 = __ldcs((const uint2*)(hp + (size_t)e0 * C) + lane);
        uint2 r1 = __ldcs((const uint2*)(hp + (size_t)e1 * C) + lane);
        uint2 r2 = __ldcs((const uint2*)(hp + (size_t)e2 * C) + lane);
        uint2 r3 = __ldcs((const uint2*)(hp + (size_t)e3 * C) + lane);
        accum(r0); accum(r1); accum(r2); accum(r3);
    }
    for (; j < cnt; j++) {
        int e = __ldg(&g_perm[s + j]);
        uint2 r = __ldcs((const uint2*)(hp + (size_t)e * C) + lane);
        accum(r);
    }
    *(float4*)(g_agg + (size_t)wg * C + cq) = acc;
}

// ---------------- BN2 + ELU -> output ----------------
__global__ void final_kernel(float* __restrict__ out, int n) {
    int g = blockIdx.x * 256 + threadIdx.x;
    if (g >= n * 32) return;
    int cq = (g & 31) * 4;
    float4 v = *(const float4*)(g_pre + (size_t)g * 4);
    float4 a = *(const float4*)(g_a2 + cq);
    float4 c = *(const float4*)(g_c2 + cq);
    float4 o;
    o.x = eluf(fmaf(v.x, a.x, c.x));
    o.y = eluf(fmaf(v.y, a.y, c.y));
    o.z = eluf(fmaf(v.z, a.z, c.z));
    o.w = eluf(fmaf(v.w, a.w, c.w));
    *(float4*)(out + (size_t)g * 4) = o;
}

// ---------------- launch ----------------
extern "C" void kernel_launch(void* const* d_in, const int* in_sizes, int n_in,
                              void* d_out, int out_size) {
    const float* x    = (const float*)d_in[0];
    const int*   ei   = (const int*)d_in[1];
    const float* ea   = (const float*)d_in[2];
    const float* w1   = (const float*)d_in[5];
    const float* b1   = (const float*)d_in[6];
    const float* bn1w = (const float*)d_in[7];
    const float* bn1b = (const float*)d_in[8];
    const float* w2   = (const float*)d_in[9];
    const float* b2   = (const float*)d_in[10];
    const float* bn2w = (const float*)d_in[11];
    const float* bn2b = (const float*)d_in[12];
    float* out = (float*)d_out;

    int n = in_sizes[0] / C;           // 50000
    int E = in_sizes[2] / C;           // 800000
    const int* row = ei;
    const int* col = ei + E;

    const int SMEM = 98304;            // 96 KB -> 2 CTAs/SM
    cudaFuncSetAttribute(mm_kernel<0>, cudaFuncAttributeMaxDynamicSharedMemorySize, SMEM);
    cudaFuncSetAttribute(mm_kernel<1>, cudaFuncAttributeMaxDynamicSharedMemorySize, SMEM);
    cudaFuncSetAttribute(mm_kernel<2>, cudaFuncAttributeMaxDynamicSharedMemorySize, SMEM);

    int nb = (n + 255) / 256;          // scan blocks (<=256 required)

    const int GRID = 296;              // 2 persistent CTAs per SM
    int ngrid = min(GRID, (n + 127) / 128);
    int egrid = min(GRID, (E + 127) / 128);

    // launch order chosen so mm_kernel<1> is launch #4 (the profiled slot)
    zero_kernel<<<(NN_MAX + 255) / 256, 256>>>();                 // 1
    prep_w<<<8, 256>>>(w1, w2);                                   // 2
    mm_kernel<0><<<ngrid, 256, SMEM>>>(x, nullptr, nullptr, n);   // 3: xa = x @ w1a^T
    mm_kernel<1><<<egrid, 256, SMEM>>>(ea, b1, row, E);           // 4: h = ea@w1b^T + xa[row] + b1

    // counting sort of edges by destination node (independent of GEMMs)
    hist_kernel<<<(E + 255) / 256, 256>>>(col, E);
    scan1_kernel<<<nb, 256>>>(n);
    scan2_kernel<<<1, 256>>>(nb);
    scan3_kernel<<<nb, 256>>>(n);
    permute_kernel<<<(E + 255) / 256, 256>>>(col, E);

    finalize_kernel<<<1, C>>>(0, bn1w, bn1b, 1.f / (float)E);

    // agg = segment_sum(elu(bn1(h)))  (CSR over fp16 h, no float atomics)
    segsum_kernel<<<(n * 32 + 255) / 256, 256>>>(n);

    // pre = x @ w2a^T + (agg/cnt) @ w2b^T + b2   (fused K=256, stats fused)
    mm_kernel<2><<<ngrid, 256, SMEM>>>(x, b2, nullptr, n);
    finalize_kernel<<<1, C>>>(1, bn2w, bn2b, 1.f / (float)n);

    final_kernel<<<(n * 32 + 255) / 256, 256>>>(out, n);
}